// round 1
// baseline (speedup 1.0000x reference)
#include <cuda_runtime.h>
#include <math.h>

#define Bn 32
#define Rr 13
#define Cc 13
#define Aa 5
#define Kk 20
#define CELL 25
#define Nn (Rr * Cc * Aa)   // 845
#define THRESH 0.5f
#define NMS_TH 0.4f

// Scratch for decoded boxes (x1,y1,x2,y2). Static device global (no allocs).
__device__ float4 g_boxes[Bn * Nn];

__device__ __forceinline__ float sigmoidf_(float v) {
    return 1.0f / (1.0f + expf(-v));
}

// One thread per (b, n) cell. Input layout (B,R,C,A*CELL) flattens so that
// cell (b,n) starts at offset (b*N + n)*CELL with its 25 values contiguous.
__global__ void region_decode_kernel(const float* __restrict__ x,
                                     const float* __restrict__ bias,
                                     float* __restrict__ out,
                                     float4* __restrict__ boxes) {
    int gid = blockIdx.x * blockDim.x + threadIdx.x;
    if (gid >= Bn * Nn) return;

    int n = gid % Nn;
    int a = n % Aa;
    int cell = n / Aa;
    int col = cell % Cc;
    int row = cell / Cc;

    const float* t = x + (size_t)gid * CELL;
    float t0 = t[0], t1 = t[1], t2 = t[2], t3 = t[3], t4 = t[4];

    float bx  = (sigmoidf_(t0) + (float)col) / (float)Cc;
    float by  = (sigmoidf_(t1) + (float)row) / (float)Rr;
    float bw  = expf(t2) * bias[2 * a]     / (float)Rr;   // matches reference (bias[0::2]/R)
    float bh  = expf(t3) * bias[2 * a + 1] / (float)Cc;   // matches reference (bias[1::2]/C)
    float obj = sigmoidf_(t4);

    // softmax over 20 class logits
    float logits[Kk];
    float m = -INFINITY;
    #pragma unroll
    for (int j = 0; j < Kk; j++) {
        logits[j] = t[5 + j];
        m = fmaxf(m, logits[j]);
    }
    float s = 0.0f;
    #pragma unroll
    for (int j = 0; j < Kk; j++) {
        logits[j] = expf(logits[j] - m);
        s += logits[j];
    }
    float inv = 1.0f / s;

    float x1 = bx - 0.5f * bw;
    float y1 = by - 0.5f * bh;
    boxes[gid] = make_float4(x1, y1, x1 + bw, y1 + bh);

    float* o = out + (size_t)gid * CELL;
    o[0] = bx; o[1] = by; o[2] = bw; o[3] = bh; o[4] = obj;
    #pragma unroll
    for (int j = 0; j < Kk; j++) {
        float p = obj * logits[j] * inv;
        o[5 + j] = (p > THRESH) ? p : 0.0f;
    }
}

// One block per (b, k). Collect valid boxes (score > 0.5) into shared, sort by
// score desc (stable tie-break by index to match jnp stable argsort), greedy
// NMS (IoU > 0.4), then zero the suppressed scores in place.
__global__ void region_nms_kernel(const float4* __restrict__ boxes,
                                  float* __restrict__ out) {
    int b = blockIdx.x / Kk;
    int k = blockIdx.x % Kk;

    __shared__ int s_cnt;
    __shared__ short s_idx[Nn];
    __shared__ float s_score[Nn];
    __shared__ float4 s_box[Nn];
    __shared__ unsigned char s_sup[Nn];

    if (threadIdx.x == 0) s_cnt = 0;
    __syncthreads();

    for (int n = threadIdx.x; n < Nn; n += blockDim.x) {
        float sc = out[((size_t)(b * Nn + n)) * CELL + 5 + k];
        if (sc > THRESH) {
            int p = atomicAdd(&s_cnt, 1);
            s_idx[p] = (short)n;
            s_score[p] = sc;
            s_box[p] = boxes[b * Nn + n];
        }
    }
    __syncthreads();

    int V = s_cnt;
    if (V <= 1) return;

    if (threadIdx.x == 0) {
        // insertion sort: score desc, idx asc on ties
        for (int i = 1; i < V; i++) {
            float sc = s_score[i];
            short id = s_idx[i];
            float4 bi = s_box[i];
            int j = i - 1;
            while (j >= 0 && (s_score[j] < sc ||
                              (s_score[j] == sc && s_idx[j] > id))) {
                s_score[j + 1] = s_score[j];
                s_idx[j + 1]   = s_idx[j];
                s_box[j + 1]   = s_box[j];
                j--;
            }
            s_score[j + 1] = sc;
            s_idx[j + 1]   = id;
            s_box[j + 1]   = bi;
        }
        for (int i = 0; i < V; i++) s_sup[i] = 0;

        for (int i = 0; i < V; i++) {
            if (s_sup[i]) continue;          // only alive boxes suppress
            float4 bi = s_box[i];
            float ai = (bi.z - bi.x) * (bi.w - bi.y);
            for (int j = i + 1; j < V; j++) {
                if (s_sup[j]) continue;
                float4 bj = s_box[j];
                float iw = fminf(bi.z, bj.z) - fmaxf(bi.x, bj.x);
                float ih = fminf(bi.w, bj.w) - fmaxf(bi.y, bj.y);
                iw = fmaxf(iw, 0.0f);
                ih = fmaxf(ih, 0.0f);
                float inter = iw * ih;
                float aj = (bj.z - bj.x) * (bj.w - bj.y);
                float uni = fmaxf(ai + aj - inter, 1e-9f);
                if (inter / uni > NMS_TH) s_sup[j] = 1;
            }
        }
        for (int i = 0; i < V; i++) {
            if (s_sup[i]) {
                out[((size_t)(b * Nn + s_idx[i])) * CELL + 5 + k] = 0.0f;
            }
        }
    }
}

extern "C" void kernel_launch(void* const* d_in, const int* in_sizes, int n_in,
                              void* d_out, int out_size) {
    const float* x    = (const float*)d_in[0];
    const float* bias = (const float*)d_in[1];
    float* out        = (float*)d_out;

    float4* boxes;
    cudaGetSymbolAddress((void**)&boxes, g_boxes);

    int total = Bn * Nn;
    int threads = 128;
    int blocks = (total + threads - 1) / threads;
    region_decode_kernel<<<blocks, threads>>>(x, bias, out, boxes);
    region_nms_kernel<<<Bn * Kk, 128>>>(boxes, out);
}

// round 2
// speedup vs baseline: 1.3266x; 1.3266x over previous
#include <cuda_runtime.h>
#include <math.h>

#define Bn 32
#define Rr 13
#define Cc 13
#define Aa 5
#define Kk 20
#define CELL 25
#define Nn 845                       // R*C*A
#define TOTAL (Bn * Nn)              // 27040
#define THRESH 0.5f
#define NMS_TH 0.4f
#define TPB 192
#define NBLK ((TOTAL + TPB - 1) / TPB)   // 141
#define NBK (Bn * Kk)                // 640
#define CAP Nn
#define SUPW ((CAP + 31) / 32)       // 27

// Static device scratch (no allocations allowed).
__device__ float        g_cs[NBK * CAP];   // candidate scores
__device__ int          g_cn[NBK * CAP];   // candidate box index n
__device__ float4       g_cb[NBK * CAP];   // candidate boxes (x1,y1,x2,y2)
__device__ int          g_cnt[NBK];        // per-(b,k) candidate counts (reset by NMS tail)
__device__ unsigned int g_done;            // done-block counter   (reset by last block)

__device__ __forceinline__ float sigmoid_(float v) {
    return 1.0f / (1.0f + __expf(-v));
}

__global__ void __launch_bounds__(TPB)
region_fused(const float* __restrict__ x,
             const float* __restrict__ bias,
             float* __restrict__ out) {
    const int tid = threadIdx.x;
    const int gid = blockIdx.x * TPB + tid;

    __shared__ int      s_cnt;
    __shared__ int      s_gid[TPB];
    __shared__ float    s_obj[TPB];
    __shared__ float4   s_box[TPB];
    __shared__ unsigned s_done;

    if (tid == 0) s_cnt = 0;
    __syncthreads();

    // ---- Phase 1: decode box/obj for every cell, write zeros for class slots,
    //      compact cells with obj > 0.5 (necessary for any class to pass).
    if (gid < TOTAL) {
        const float* t = x + (size_t)gid * CELL;
        int n    = gid % Nn;
        int a    = n % Aa;
        int cell = n / Aa;
        int col  = cell % Cc;
        int row  = cell / Cc;

        float bx  = (sigmoid_(t[0]) + (float)col) * (1.0f / (float)Cc);
        float by  = (sigmoid_(t[1]) + (float)row) * (1.0f / (float)Rr);
        float bw  = __expf(t[2]) * bias[2 * a]     * (1.0f / (float)Rr);
        float bh  = __expf(t[3]) * bias[2 * a + 1] * (1.0f / (float)Cc);
        float obj = sigmoid_(t[4]);

        float* o = out + (size_t)gid * CELL;
        o[0] = bx; o[1] = by; o[2] = bw; o[3] = bh; o[4] = obj;
        #pragma unroll
        for (int j = 0; j < Kk; j++) o[5 + j] = 0.0f;

        if (obj > THRESH) {
            int p = atomicAdd(&s_cnt, 1);
            s_gid[p] = gid;
            s_obj[p] = obj;
            float x1 = bx - 0.5f * bw;
            float y1 = by - 0.5f * bh;
            s_box[p] = make_float4(x1, y1, x1 + bw, y1 + bh);
        }
    }
    __syncthreads();

    // ---- Phase 2: dense softmax over compacted cells; push rare candidates.
    const int cnt = s_cnt;
    for (int i = tid; i < cnt; i += TPB) {
        int g2    = s_gid[i];
        float obj = s_obj[i];
        const float* t = x + (size_t)g2 * CELL + 5;

        float e[Kk];
        float s = 0.0f;
        #pragma unroll
        for (int j = 0; j < Kk; j++) { e[j] = __expf(t[j]); s += e[j]; }
        float inv = 1.0f / s;

        int b2 = g2 / Nn;
        int n2 = g2 % Nn;
        #pragma unroll
        for (int j = 0; j < Kk; j++) {
            float p = obj * e[j] * inv;
            if (p > THRESH) {
                out[(size_t)g2 * CELL + 5 + j] = p;
                int slot = b2 * Kk + j;
                int q = atomicAdd(&g_cnt[slot], 1);
                g_cs[slot * CAP + q] = p;
                g_cn[slot * CAP + q] = n2;
                g_cb[slot * CAP + q] = s_box[i];
            }
        }
    }

    // ---- Done-barrier: last finishing block runs the (tiny) NMS tail.
    __threadfence();
    __syncthreads();
    if (tid == 0) s_done = atomicAdd(&g_done, 1u);
    __syncthreads();
    if (s_done != (unsigned)(NBLK - 1)) return;

    if (tid == 0) g_done = 0;   // reset for next graph replay
    __threadfence();

    // ---- Phase 3 (last block only): greedy NMS per (b,k) over compacted lists.
    for (int t = tid; t < NBK; t += TPB) {
        int V = g_cnt[t];
        g_cnt[t] = 0;           // reset for next replay
        if (V <= 1) continue;

        int b = t / Kk;
        int k = t % Kk;
        const float*  cs = g_cs + (size_t)t * CAP;
        const int*    cn = g_cn + (size_t)t * CAP;
        const float4* cb = g_cb + (size_t)t * CAP;

        unsigned sup[SUPW], used[SUPW];
        int nw = (V + 31) >> 5;
        for (int w = 0; w < nw; w++) { sup[w] = 0u; used[w] = 0u; }

        // Selection-based greedy: process in (score desc, index asc) order.
        for (int it = 0; it < V; it++) {
            int   best = -1, bn = 0x7fffffff;
            float bs = -1.0f;
            for (int j = 0; j < V; j++) {
                if ((used[j >> 5] >> (j & 31)) & 1u) continue;
                float sj = cs[j];
                int   nj = cn[j];
                if (sj > bs || (sj == bs && nj < bn)) { best = j; bs = sj; bn = nj; }
            }
            used[best >> 5] |= 1u << (best & 31);
            if ((sup[best >> 5] >> (best & 31)) & 1u) continue;  // not alive

            float4 bb = cb[best];
            float  ab = (bb.z - bb.x) * (bb.w - bb.y);
            for (int j = 0; j < V; j++) {
                if ((used[j >> 5] >> (j & 31)) & 1u) continue;
                if ((sup[j >> 5]  >> (j & 31)) & 1u) continue;
                float4 cj = cb[j];
                float iw = fminf(bb.z, cj.z) - fmaxf(bb.x, cj.x);
                float ih = fminf(bb.w, cj.w) - fmaxf(bb.y, cj.y);
                iw = fmaxf(iw, 0.0f);
                ih = fmaxf(ih, 0.0f);
                float inter = iw * ih;
                float aj    = (cj.z - cj.x) * (cj.w - cj.y);
                float uni   = fmaxf(ab + aj - inter, 1e-9f);
                if (inter / uni > NMS_TH) sup[j >> 5] |= 1u << (j & 31);
            }
        }
        for (int j = 0; j < V; j++) {
            if ((sup[j >> 5] >> (j & 31)) & 1u)
                out[((size_t)(b * Nn + cn[j])) * CELL + 5 + k] = 0.0f;
        }
    }
}

extern "C" void kernel_launch(void* const* d_in, const int* in_sizes, int n_in,
                              void* d_out, int out_size) {
    const float* x    = (const float*)d_in[0];
    const float* bias = (const float*)d_in[1];
    float* out        = (float*)d_out;
    region_fused<<<NBLK, TPB>>>(x, bias, out);
}